// round 9
// baseline (speedup 1.0000x reference)
#include <cuda_runtime.h>

#define HW 65536            // 256*256
#define IMGW 256
#define NWIN 32
#define SCALE 0.25f

typedef unsigned long long ull;

__device__ float g_qkv[2 * 288 * HW];
__device__ float g_att[2 * 96 * HW];

// ---------- f32x2 helpers ----------
__device__ __forceinline__ ull pack2(float a, float b) {
    ull r; asm("mov.b64 %0,{%1,%2};" : "=l"(r) : "f"(a), "f"(b)); return r;
}
__device__ __forceinline__ float2 unpack2(ull v) {
    float2 r; asm("mov.b64 {%0,%1},%2;" : "=f"(r.x), "=f"(r.y) : "l"(v)); return r;
}
__device__ __forceinline__ ull ffma2(ull a, ull b, ull c) {
    ull d; asm("fma.rn.f32x2 %0,%1,%2,%3;" : "=l"(d) : "l"(a), "l"(b), "l"(c)); return d;
}
__device__ __forceinline__ ull fadd2(ull a, ull b) {
    ull d; asm("add.rn.f32x2 %0,%1,%2;" : "=l"(d) : "l"(a), "l"(b)); return d;
}
__device__ __forceinline__ void lds2x64(ull& a, ull& b, unsigned addr) {
    asm("ld.shared.v2.u64 {%0,%1},[%2];" : "=l"(a), "=l"(b) : "r"(addr));
}

// ---------- tf32 helpers ----------
__device__ __forceinline__ float tf32_round(float x) {
    unsigned u; asm("cvt.rna.tf32.f32 %0, %1;" : "=r"(u) : "f"(x));
    return __uint_as_float(u);
}
__device__ __forceinline__ void mma_tf32(float& d0, float& d1, float& d2, float& d3,
                                         unsigned a0, unsigned a1, unsigned a2, unsigned a3,
                                         unsigned b0, unsigned b1) {
    asm("mma.sync.aligned.m16n8k8.row.col.f32.tf32.tf32.f32 "
        "{%0,%1,%2,%3},{%4,%5,%6,%7},{%8,%9},{%0,%1,%2,%3};"
        : "+f"(d0), "+f"(d1), "+f"(d2), "+f"(d3)
        : "r"(a0), "r"(a1), "r"(a2), "r"(a3), "r"(b0), "r"(b1));
}

// ---------------------------------------------------------------------------
// Pointwise GEMM via tensor cores (3xTF32) — measured R7: 222us + ~74us.
// ---------------------------------------------------------------------------
template <int OC>
__global__ __launch_bounds__(256) void mma_gemm(
    const float* __restrict__ X, const float* __restrict__ W,
    const float* __restrict__ Bias, float* __restrict__ Y)
{
    __shared__ __align__(16) float2 XPhi[2][4][260];
    __shared__ __align__(16) float2 XPlo[2][4][260];
    __shared__ __align__(16) float2 WPhi[2][4][36];
    __shared__ __align__(16) float2 WPlo[2][4][36];

    const int b   = blockIdx.z;
    const int o0  = blockIdx.y * 32;
    const int p0  = blockIdx.x * 256;
    const int tid = threadIdx.x;
    const int warp = tid >> 5;
    const int lane = tid & 31;
    const int g = lane >> 2;
    const int t = lane & 3;
    const int om = (warp >> 2) * 16;
    const int nq = (warp & 3) * 64;

    float acc[8][4];
#pragma unroll
    for (int nb = 0; nb < 8; nb++)
#pragma unroll
        for (int r = 0; r < 4; r++) acc[nb][r] = 0.f;

    for (int kc = 0; kc < 96; kc += 16) {
        __syncthreads();
#pragma unroll
        for (int pss = 0; pss < 4; pss++) {
            int j  = tid + pss * 256;
            int k  = j >> 6;
            int n4 = j & 63;
            float4 xv = *(const float4*)(X + (size_t)(b * 96 + kc + k) * HW + p0 + n4 * 4);
            int s  = k >> 3;
            int kk = k & 7;
            int tt = kk & 3;
            int comp = kk >> 2;
            float vals[4] = {xv.x, xv.y, xv.z, xv.w};
#pragma unroll
            for (int c = 0; c < 4; c++) {
                float v  = vals[c];
                float hi = tf32_round(v);
                float lo = tf32_round(v - hi);
                int n = n4 * 4 + c;
                (&XPhi[s][tt][n].x)[comp] = hi;
                (&XPlo[s][tt][n].x)[comp] = lo;
            }
        }
#pragma unroll
        for (int pss = 0; pss < 2; pss++) {
            int i = tid + pss * 256;
            int o = i & 31;
            int k = i >> 5;
            float v  = W[(o0 + o) * 96 + kc + k];
            float hi = tf32_round(v);
            float lo = tf32_round(v - hi);
            int s  = k >> 3;
            int kk = k & 7;
            int tt = kk & 3;
            int comp = kk >> 2;
            (&WPhi[s][tt][o].x)[comp] = hi;
            (&WPlo[s][tt][o].x)[comp] = lo;
        }
        __syncthreads();

#pragma unroll
        for (int s = 0; s < 2; s++) {
            float2 ah0 = WPhi[s][t][om + g];
            float2 ah1 = WPhi[s][t][om + g + 8];
            float2 al0 = WPlo[s][t][om + g];
            float2 al1 = WPlo[s][t][om + g + 8];
            unsigned Ah0 = __float_as_uint(ah0.x), Ah1 = __float_as_uint(ah1.x);
            unsigned Ah2 = __float_as_uint(ah0.y), Ah3 = __float_as_uint(ah1.y);
            unsigned Al0 = __float_as_uint(al0.x), Al1 = __float_as_uint(al1.x);
            unsigned Al2 = __float_as_uint(al0.y), Al3 = __float_as_uint(al1.y);

#pragma unroll
            for (int nb = 0; nb < 8; nb++) {
                int n = nq + nb * 8 + g;
                float2 bh = XPhi[s][t][n];
                float2 bl = XPlo[s][t][n];
                unsigned Bh0 = __float_as_uint(bh.x), Bh1 = __float_as_uint(bh.y);
                unsigned Bl0 = __float_as_uint(bl.x), Bl1 = __float_as_uint(bl.y);
                mma_tf32(acc[nb][0], acc[nb][1], acc[nb][2], acc[nb][3],
                         Ah0, Ah1, Ah2, Ah3, Bh0, Bh1);
                mma_tf32(acc[nb][0], acc[nb][1], acc[nb][2], acc[nb][3],
                         Ah0, Ah1, Ah2, Ah3, Bl0, Bl1);
                mma_tf32(acc[nb][0], acc[nb][1], acc[nb][2], acc[nb][3],
                         Al0, Al1, Al2, Al3, Bh0, Bh1);
            }
        }
    }

    const int r0 = o0 + om + g;
    const int r1 = r0 + 8;
    const float bias0 = Bias[r0];
    const float bias1 = Bias[r1];
    float* y0 = Y + (size_t)(b * OC + r0) * HW + p0 + nq + t * 2;
    float* y1 = Y + (size_t)(b * OC + r1) * HW + p0 + nq + t * 2;
#pragma unroll
    for (int nb = 0; nb < 8; nb++) {
        *(float2*)(y0 + nb * 8) = make_float2(acc[nb][0] + bias0, acc[nb][1] + bias0);
        *(float2*)(y1 + nb * 8) = make_float2(acc[nb][2] + bias1, acc[nb][3] + bias1);
    }
}

// ---------------------------------------------------------------------------
// Window attention v2: block = window x 2 heads, 64 threads (warp = head),
// each thread handles TWO queries (lane, lane+32). Halves per-key LDS traffic
// and doubles per-warp ILP (two independent logit chains).
// ---------------------------------------------------------------------------
__global__ __launch_bounds__(64) void attn_kernel(
    const float* __restrict__ rel_h, const float* __restrict__ rel_w)
{
    __shared__ __align__(16) float ksm[2 * 144 * 20];
    __shared__ __align__(16) float vsm[2 * 144 * 20];
    __shared__ __align__(16) float rhs_[23 * 16];
    __shared__ __align__(16) float rws_[23 * 16];

    const int hp  = blockIdx.x % 3;
    const int win = blockIdx.x / 3;
    const int b   = win >> 10;
    const int wy  = (win >> 5) & 31;
    const int wx  = win & 31;
    const int tid = threadIdx.x;
    const int h0  = hp * 2;

    for (int i = tid; i < 23 * 16; i += 64) {
        rhs_[i] = rel_h[i];
        rws_[i] = rel_w[i];
    }

    // Stage K and V halo tiles (zero outside image).
    const int y0 = wy * 8 - 2, x0 = wx * 8 - 2;
    for (int i = tid; i < 2 * 16 * 144; i += 64) {
        int j  = i % 12;
        int tt = i / 12;
        int ii = tt % 12;  tt /= 12;
        int d  = tt & 15;
        int hh = tt >> 4;
        int gy = y0 + ii, gx = x0 + j;
        float kv = 0.f, vv = 0.f;
        if ((unsigned)gy < 256u && (unsigned)gx < 256u) {
            const float* p = g_qkv +
                ((size_t)b * 288 + 96 + (h0 + hh) * 16 + d) * HW + gy * IMGW + gx;
            kv = p[0];
            vv = p[(size_t)96 * HW];
        }
        int si = (hh * 144 + ii * 12 + j) * 20 + d;
        ksm[si] = kv;
        vsm[si] = vv;
    }
    __syncthreads();

    const int hh   = tid >> 5;          // warp = head
    const int head = h0 + hh;
    const int lane = tid & 31;
    // query 0: qi = lane; query 1: qi = lane + 32  (x1 = x0 + 4, y1 = y0)
    const int x0q  = lane >> 3, yq = lane & 7;
    const int x1q  = x0q + 4;
    const int gy0  = wy * 8 + x0q, gx_ = wx * 8 + yq;
    const int gy1  = wy * 8 + x1q;

    // load both q vectors as f32x2 pairs
    ull q0[8], q1[8];
    {
        const float* qb = g_qkv + ((size_t)b * 288 + head * 16) * HW;
        const float* qa = qb + gy0 * IMGW + gx_;
        const float* qc = qb + gy1 * IMGW + gx_;
#pragma unroll
        for (int d = 0; d < 8; d++) {
            q0[d] = pack2(SCALE * qa[(size_t)(2 * d) * HW], SCALE * qa[(size_t)(2 * d + 1) * HW]);
            q1[d] = pack2(SCALE * qc[(size_t)(2 * d) * HW], SCALE * qc[(size_t)(2 * d + 1) * HW]);
        }
    }

    // Column rel dots (rws row shared between the two queries: same y)
    float Bv0[12], Bv1[12];
#pragma unroll
    for (int kj = 0; kj < 12; kj++) {
        const ull* rw = (const ull*)&rws_[(kj - yq + 11) * 16];
        ull a0 = 0, a1 = 0, b0 = 0, b1 = 0;
#pragma unroll
        for (int d = 0; d < 8; d += 2) {
            ull r0 = rw[d], r1 = rw[d + 1];
            a0 = ffma2(q0[d], r0, a0);  a1 = ffma2(q0[d + 1], r1, a1);
            b0 = ffma2(q1[d], r0, b0);  b1 = ffma2(q1[d + 1], r1, b1);
        }
        float2 fa = unpack2(fadd2(a0, a1));
        float2 fb = unpack2(fadd2(b0, b1));
        Bv0[kj] = fa.x + fa.y;
        Bv1[kj] = fb.x + fb.y;
    }

    float s0 = 0.f, s1 = 0.f;
    ull acc0[8] = {}, acc1[8] = {};
    const unsigned kaddr = (unsigned)__cvta_generic_to_shared(&ksm[hh * 144 * 20]);
    const unsigned vaddr = (unsigned)__cvta_generic_to_shared(&vsm[hh * 144 * 20]);

    for (int ki = 0; ki < 12; ki++) {
        // Row rel dots (rhs rows differ between queries: x1 = x0 + 4)
        float aki0, aki1;
        {
            const ull* rh0 = (const ull*)&rhs_[(ki - x0q + 11) * 16];
            const ull* rh1 = (const ull*)&rhs_[(ki - x1q + 11) * 16];
            ull a0 = 0, a1 = 0, b0 = 0, b1 = 0;
#pragma unroll
            for (int d = 0; d < 8; d += 2) {
                a0 = ffma2(q0[d], rh0[d], a0);  a1 = ffma2(q0[d + 1], rh0[d + 1], a1);
                b0 = ffma2(q1[d], rh1[d], b0);  b1 = ffma2(q1[d + 1], rh1[d + 1], b1);
            }
            float2 fa = unpack2(fadd2(a0, a1));
            float2 fb = unpack2(fadd2(b0, b1));
            aki0 = fa.x + fa.y;
            aki1 = fb.x + fb.y;
        }

        const unsigned kro = kaddr + ki * 12 * 80;
        const unsigned vro = vaddr + ki * 12 * 80;
#pragma unroll
        for (int kj = 0; kj < 12; kj++) {
            ull k0, k1, k2, k3, k4, k5, k6, k7;
            lds2x64(k0, k1, kro + kj * 80);
            lds2x64(k2, k3, kro + kj * 80 + 16);
            lds2x64(k4, k5, kro + kj * 80 + 32);
            lds2x64(k6, k7, kro + kj * 80 + 48);

            // two independent logit chains (rel terms ride the pair)
            ull la = pack2(aki0, Bv0[kj]);
            ull lb = 0;
            ull lc = pack2(aki1, Bv1[kj]);
            ull ld = 0;
            la = ffma2(q0[0], k0, la);  lb = ffma2(q0[1], k1, lb);
            lc = ffma2(q1[0], k0, lc);  ld = ffma2(q1[1], k1, ld);
            la = ffma2(q0[2], k2, la);  lb = ffma2(q0[3], k3, lb);
            lc = ffma2(q1[2], k2, lc);  ld = ffma2(q1[3], k3, ld);
            la = ffma2(q0[4], k4, la);  lb = ffma2(q0[5], k5, lb);
            lc = ffma2(q1[4], k4, lc);  ld = ffma2(q1[5], k5, ld);
            la = ffma2(q0[6], k6, la);  lb = ffma2(q0[7], k7, lb);
            lc = ffma2(q1[6], k6, lc);  ld = ffma2(q1[7], k7, ld);
            float2 lf0 = unpack2(fadd2(la, lb));
            float2 lf1 = unpack2(fadd2(lc, ld));

            float p0 = __expf(lf0.x + lf0.y);
            float p1 = __expf(lf1.x + lf1.y);
            s0 += p0;
            s1 += p1;
            ull pd0 = pack2(p0, p0);
            ull pd1 = pack2(p1, p1);

            ull v0, v1, v2, v3, v4, v5, v6, v7;
            lds2x64(v0, v1, vro + kj * 80);
            lds2x64(v2, v3, vro + kj * 80 + 16);
            lds2x64(v4, v5, vro + kj * 80 + 32);
            lds2x64(v6, v7, vro + kj * 80 + 48);
            acc0[0] = ffma2(pd0, v0, acc0[0]);  acc1[0] = ffma2(pd1, v0, acc1[0]);
            acc0[1] = ffma2(pd0, v1, acc0[1]);  acc1[1] = ffma2(pd1, v1, acc1[1]);
            acc0[2] = ffma2(pd0, v2, acc0[2]);  acc1[2] = ffma2(pd1, v2, acc1[2]);
            acc0[3] = ffma2(pd0, v3, acc0[3]);  acc1[3] = ffma2(pd1, v3, acc1[3]);
            acc0[4] = ffma2(pd0, v4, acc0[4]);  acc1[4] = ffma2(pd1, v4, acc1[4]);
            acc0[5] = ffma2(pd0, v5, acc0[5]);  acc1[5] = ffma2(pd1, v5, acc1[5]);
            acc0[6] = ffma2(pd0, v6, acc0[6]);  acc1[6] = ffma2(pd1, v6, acc1[6]);
            acc0[7] = ffma2(pd0, v7, acc0[7]);  acc1[7] = ffma2(pd1, v7, acc1[7]);
        }
    }

    float inv0 = 1.f / s0;
    float inv1 = 1.f / s1;
    float* ob = g_att + ((size_t)b * 96 + head * 16) * HW;
    float* o0 = ob + gy0 * IMGW + gx_;
    float* o1 = ob + gy1 * IMGW + gx_;
#pragma unroll
    for (int j = 0; j < 8; j++) {
        float2 f0 = unpack2(acc0[j]);
        float2 f1 = unpack2(acc1[j]);
        o0[(size_t)(2 * j) * HW]     = f0.x * inv0;
        o0[(size_t)(2 * j + 1) * HW] = f0.y * inv0;
        o1[(size_t)(2 * j) * HW]     = f1.x * inv1;
        o1[(size_t)(2 * j + 1) * HW] = f1.y * inv1;
    }
}

// ---------------------------------------------------------------------------
extern "C" void kernel_launch(void* const* d_in, const int* in_sizes, int n_in,
                              void* d_out, int out_size)
{
    (void)in_sizes; (void)n_in; (void)out_size;
    const float* x      = (const float*)d_in[0];
    const float* qkv_w  = (const float*)d_in[1];
    const float* qkv_b  = (const float*)d_in[2];
    const float* proj_w = (const float*)d_in[3];
    const float* proj_b = (const float*)d_in[4];
    const float* rel_h  = (const float*)d_in[5];
    const float* rel_w  = (const float*)d_in[6];
    float* out = (float*)d_out;

    float* qkv_ptr = nullptr;
    float* att_ptr = nullptr;
    cudaGetSymbolAddress((void**)&qkv_ptr, g_qkv);
    cudaGetSymbolAddress((void**)&att_ptr, g_att);

    // 1) QKV pointwise GEMM (tensor cores, 3xTF32): (2,96,HW) -> (2,288,HW)
    mma_gemm<288><<<dim3(HW / 256, 288 / 32, 2), 256>>>(x, qkv_w, qkv_b, qkv_ptr);

    // 2) Windowed halo attention with rel-pos + softmax -> (2,96,HW)
    attn_kernel<<<2 * NWIN * NWIN * 3, 64>>>(rel_h, rel_w);

    // 3) Output projection (tensor cores): (2,96,HW) -> (2,96,HW)
    mma_gemm<96><<<dim3(HW / 256, 96 / 32, 2), 256>>>(att_ptr, proj_w, proj_b, out);
}

// round 10
// speedup vs baseline: 1.1731x; 1.1731x over previous
#include <cuda_runtime.h>

#define HW 65536            // 256*256
#define IMGW 256
#define NWIN 32
#define SCALE 0.25f

typedef unsigned long long ull;

__device__ float g_qkv[2 * 288 * HW];
__device__ float g_att[2 * 96 * HW];

// ---------- f32x2 helpers ----------
__device__ __forceinline__ ull pack2(float a, float b) {
    ull r; asm("mov.b64 %0,{%1,%2};" : "=l"(r) : "f"(a), "f"(b)); return r;
}
__device__ __forceinline__ float2 unpack2(ull v) {
    float2 r; asm("mov.b64 {%0,%1},%2;" : "=f"(r.x), "=f"(r.y) : "l"(v)); return r;
}
__device__ __forceinline__ ull ffma2(ull a, ull b, ull c) {
    ull d; asm("fma.rn.f32x2 %0,%1,%2,%3;" : "=l"(d) : "l"(a), "l"(b), "l"(c)); return d;
}
__device__ __forceinline__ ull fadd2(ull a, ull b) {
    ull d; asm("add.rn.f32x2 %0,%1,%2;" : "=l"(d) : "l"(a), "l"(b)); return d;
}
__device__ __forceinline__ void lds2x64(ull& a, ull& b, unsigned addr) {
    asm("ld.shared.v2.u64 {%0,%1},[%2];" : "=l"(a), "=l"(b) : "r"(addr));
}

// ---------- tf32 helpers ----------
__device__ __forceinline__ float tf32_round(float x) {
    unsigned u; asm("cvt.rna.tf32.f32 %0, %1;" : "=r"(u) : "f"(x));
    return __uint_as_float(u);
}
__device__ __forceinline__ void mma_tf32(float& d0, float& d1, float& d2, float& d3,
                                         unsigned a0, unsigned a1, unsigned a2, unsigned a3,
                                         unsigned b0, unsigned b1) {
    asm("mma.sync.aligned.m16n8k8.row.col.f32.tf32.tf32.f32 "
        "{%0,%1,%2,%3},{%4,%5,%6,%7},{%8,%9},{%0,%1,%2,%3};"
        : "+f"(d0), "+f"(d1), "+f"(d2), "+f"(d3)
        : "r"(a0), "r"(a1), "r"(a2), "r"(a3), "r"(b0), "r"(b1));
}

// ---------------------------------------------------------------------------
// Pointwise GEMM via tensor cores (3xTF32), v2 smem layout:
// plain component arrays [s][t][comp][n] -> staging stores are conflict-free
// STS.128; fragment loads are conflict-free LDS.32 (pads 260 / 36 chosen so
// bank = 8t + 4comp + n  covers all 32 banks per instruction).
// ---------------------------------------------------------------------------
template <int OC>
__global__ __launch_bounds__(256) void mma_gemm(
    const float* __restrict__ X, const float* __restrict__ W,
    const float* __restrict__ Bias, float* __restrict__ Y)
{
    __shared__ __align__(16) float XPhi[2][4][2][260];
    __shared__ __align__(16) float XPlo[2][4][2][260];
    __shared__ __align__(16) float WPhi[2][4][2][36];
    __shared__ __align__(16) float WPlo[2][4][2][36];

    const int b   = blockIdx.z;
    const int o0  = blockIdx.y * 32;
    const int p0  = blockIdx.x * 256;
    const int tid = threadIdx.x;
    const int warp = tid >> 5;
    const int lane = tid & 31;
    const int g = lane >> 2;
    const int t = lane & 3;
    const int om = (warp >> 2) * 16;
    const int nq = (warp & 3) * 64;

    float acc[8][4];
#pragma unroll
    for (int nb = 0; nb < 8; nb++)
#pragma unroll
        for (int r = 0; r < 4; r++) acc[nb][r] = 0.f;

    for (int kc = 0; kc < 96; kc += 16) {
        __syncthreads();
        // ---- stage X chunk [16][256]: hi/lo split, vectorized stores ----
#pragma unroll
        for (int pss = 0; pss < 4; pss++) {
            int j  = tid + pss * 256;          // float4 slot
            int k  = j >> 6;                   // 0..15
            int n4 = j & 63;
            float4 xv = *(const float4*)(X + (size_t)(b * 96 + kc + k) * HW + p0 + n4 * 4);
            int s  = k >> 3;
            int kk = k & 7;
            int tt = kk & 3;
            int comp = kk >> 2;
            float4 hi4, lo4;
            hi4.x = tf32_round(xv.x);  lo4.x = tf32_round(xv.x - hi4.x);
            hi4.y = tf32_round(xv.y);  lo4.y = tf32_round(xv.y - hi4.y);
            hi4.z = tf32_round(xv.z);  lo4.z = tf32_round(xv.z - hi4.z);
            hi4.w = tf32_round(xv.w);  lo4.w = tf32_round(xv.w - hi4.w);
            *(float4*)&XPhi[s][tt][comp][n4 * 4] = hi4;
            *(float4*)&XPlo[s][tt][comp][n4 * 4] = lo4;
        }
        // ---- stage W chunk [16][32] ----
#pragma unroll
        for (int pss = 0; pss < 2; pss++) {
            int i = tid + pss * 256;
            int o = i & 31;
            int k = i >> 5;
            float v  = W[(o0 + o) * 96 + kc + k];
            float hi = tf32_round(v);
            float lo = tf32_round(v - hi);
            int s  = k >> 3;
            int kk = k & 7;
            int tt = kk & 3;
            int comp = kk >> 2;
            WPhi[s][tt][comp][o] = hi;
            WPlo[s][tt][comp][o] = lo;
        }
        __syncthreads();

#pragma unroll
        for (int s = 0; s < 2; s++) {
            unsigned Ah0 = __float_as_uint(WPhi[s][t][0][om + g]);
            unsigned Ah1 = __float_as_uint(WPhi[s][t][0][om + g + 8]);
            unsigned Ah2 = __float_as_uint(WPhi[s][t][1][om + g]);
            unsigned Ah3 = __float_as_uint(WPhi[s][t][1][om + g + 8]);
            unsigned Al0 = __float_as_uint(WPlo[s][t][0][om + g]);
            unsigned Al1 = __float_as_uint(WPlo[s][t][0][om + g + 8]);
            unsigned Al2 = __float_as_uint(WPlo[s][t][1][om + g]);
            unsigned Al3 = __float_as_uint(WPlo[s][t][1][om + g + 8]);

#pragma unroll
            for (int nb = 0; nb < 8; nb++) {
                int n = nq + nb * 8 + g;
                unsigned Bh0 = __float_as_uint(XPhi[s][t][0][n]);
                unsigned Bh1 = __float_as_uint(XPhi[s][t][1][n]);
                unsigned Bl0 = __float_as_uint(XPlo[s][t][0][n]);
                unsigned Bl1 = __float_as_uint(XPlo[s][t][1][n]);
                mma_tf32(acc[nb][0], acc[nb][1], acc[nb][2], acc[nb][3],
                         Ah0, Ah1, Ah2, Ah3, Bh0, Bh1);
                mma_tf32(acc[nb][0], acc[nb][1], acc[nb][2], acc[nb][3],
                         Ah0, Ah1, Ah2, Ah3, Bl0, Bl1);
                mma_tf32(acc[nb][0], acc[nb][1], acc[nb][2], acc[nb][3],
                         Al0, Al1, Al2, Al3, Bh0, Bh1);
            }
        }
    }

    const int r0 = o0 + om + g;
    const int r1 = r0 + 8;
    const float bias0 = Bias[r0];
    const float bias1 = Bias[r1];
    float* y0 = Y + (size_t)(b * OC + r0) * HW + p0 + nq + t * 2;
    float* y1 = Y + (size_t)(b * OC + r1) * HW + p0 + nq + t * 2;
#pragma unroll
    for (int nb = 0; nb < 8; nb++) {
        *(float2*)(y0 + nb * 8) = make_float2(acc[nb][0] + bias0, acc[nb][1] + bias0);
        *(float2*)(y1 + nb * 8) = make_float2(acc[nb][2] + bias1, acc[nb][3] + bias1);
    }
}

// ---------------------------------------------------------------------------
// Window attention — R7 version (128 threads, measured ~343us). f32x2 inner.
// ---------------------------------------------------------------------------
__global__ __launch_bounds__(128, 4) void attn_kernel(
    const float* __restrict__ rel_h, const float* __restrict__ rel_w)
{
    __shared__ __align__(16) float ksm[2 * 144 * 20];
    __shared__ __align__(16) float vsm[2 * 144 * 20];
    __shared__ __align__(16) float rhs_[23 * 16];
    __shared__ __align__(16) float rws_[23 * 16];

    const int hp  = blockIdx.x % 3;
    const int win = blockIdx.x / 3;
    const int b   = win >> 10;
    const int wy  = (win >> 5) & 31;
    const int wx  = win & 31;
    const int tid = threadIdx.x;
    const int h0  = hp * 2;

    for (int i = tid; i < 23 * 16; i += 128) {
        rhs_[i] = rel_h[i];
        rws_[i] = rel_w[i];
    }

    const int y0 = wy * 8 - 2, x0 = wx * 8 - 2;
    for (int i = tid; i < 2 * 16 * 144; i += 128) {
        int j  = i % 12;
        int tt = i / 12;
        int ii = tt % 12;  tt /= 12;
        int d  = tt & 15;
        int hh = tt >> 4;
        int gy = y0 + ii, gx = x0 + j;
        float kv = 0.f, vv = 0.f;
        if ((unsigned)gy < 256u && (unsigned)gx < 256u) {
            const float* p = g_qkv +
                ((size_t)b * 288 + 96 + (h0 + hh) * 16 + d) * HW + gy * IMGW + gx;
            kv = p[0];
            vv = p[(size_t)96 * HW];
        }
        int si = (hh * 144 + ii * 12 + j) * 20 + d;
        ksm[si] = kv;
        vsm[si] = vv;
    }
    __syncthreads();

    const int hh   = tid >> 6;
    const int head = h0 + hh;
    const int qi   = tid & 63;
    const int x    = qi >> 3, y = qi & 7;
    const int gy   = wy * 8 + x, gx = wx * 8 + y;

    ull qp[8];
    {
        const float* qb = g_qkv + ((size_t)b * 288 + head * 16) * HW + gy * IMGW + gx;
#pragma unroll
        for (int d = 0; d < 8; d++) {
            float a = SCALE * qb[(size_t)(2 * d) * HW];
            float c = SCALE * qb[(size_t)(2 * d + 1) * HW];
            qp[d] = pack2(a, c);
        }
    }

    float Bv[12];
#pragma unroll
    for (int kj = 0; kj < 12; kj++) {
        const ull* rw = (const ull*)&rws_[(kj - y + 11) * 16];
        ull s0 = 0, s1 = 0;
#pragma unroll
        for (int d = 0; d < 8; d += 2) {
            s0 = ffma2(qp[d],     rw[d],     s0);
            s1 = ffma2(qp[d + 1], rw[d + 1], s1);
        }
        float2 f = unpack2(fadd2(s0, s1));
        Bv[kj] = f.x + f.y;
    }

    float s = 0.f;
    ull acc[8] = {};
    const unsigned kaddr = (unsigned)__cvta_generic_to_shared(&ksm[hh * 144 * 20]);
    const unsigned vaddr = (unsigned)__cvta_generic_to_shared(&vsm[hh * 144 * 20]);

    for (int ki = 0; ki < 12; ki++) {
        float aki;
        {
            const ull* rh = (const ull*)&rhs_[(ki - x + 11) * 16];
            ull s0 = 0, s1 = 0;
#pragma unroll
            for (int d = 0; d < 8; d += 2) {
                s0 = ffma2(qp[d],     rh[d],     s0);
                s1 = ffma2(qp[d + 1], rh[d + 1], s1);
            }
            float2 f = unpack2(fadd2(s0, s1));
            aki = f.x + f.y;
        }

        const unsigned kro = kaddr + ki * 12 * 80;
        const unsigned vro = vaddr + ki * 12 * 80;
#pragma unroll
        for (int kj = 0; kj < 12; kj++) {
            ull k0, k1, k2, k3, k4, k5, k6, k7;
            lds2x64(k0, k1, kro + kj * 80);
            lds2x64(k2, k3, kro + kj * 80 + 16);
            lds2x64(k4, k5, kro + kj * 80 + 32);
            lds2x64(k6, k7, kro + kj * 80 + 48);

            ull la = pack2(aki, Bv[kj]);
            ull lb = 0;
            la = ffma2(qp[0], k0, la);  lb = ffma2(qp[1], k1, lb);
            la = ffma2(qp[2], k2, la);  lb = ffma2(qp[3], k3, lb);
            la = ffma2(qp[4], k4, la);  lb = ffma2(qp[5], k5, lb);
            la = ffma2(qp[6], k6, la);  lb = ffma2(qp[7], k7, lb);
            float2 lf = unpack2(fadd2(la, lb));

            float p = __expf(lf.x + lf.y);
            s += p;
            ull pd = pack2(p, p);

            ull v0, v1, v2, v3, v4, v5, v6, v7;
            lds2x64(v0, v1, vro + kj * 80);
            lds2x64(v2, v3, vro + kj * 80 + 16);
            lds2x64(v4, v5, vro + kj * 80 + 32);
            lds2x64(v6, v7, vro + kj * 80 + 48);
            acc[0] = ffma2(pd, v0, acc[0]);
            acc[1] = ffma2(pd, v1, acc[1]);
            acc[2] = ffma2(pd, v2, acc[2]);
            acc[3] = ffma2(pd, v3, acc[3]);
            acc[4] = ffma2(pd, v4, acc[4]);
            acc[5] = ffma2(pd, v5, acc[5]);
            acc[6] = ffma2(pd, v6, acc[6]);
            acc[7] = ffma2(pd, v7, acc[7]);
        }
    }

    float inv = 1.f / s;
    float* outp = g_att + ((size_t)b * 96 + head * 16) * HW + gy * IMGW + gx;
#pragma unroll
    for (int j = 0; j < 8; j++) {
        float2 f = unpack2(acc[j]);
        outp[(size_t)(2 * j) * HW]     = f.x * inv;
        outp[(size_t)(2 * j + 1) * HW] = f.y * inv;
    }
}

// ---------------------------------------------------------------------------
extern "C" void kernel_launch(void* const* d_in, const int* in_sizes, int n_in,
                              void* d_out, int out_size)
{
    (void)in_sizes; (void)n_in; (void)out_size;
    const float* x      = (const float*)d_in[0];
    const float* qkv_w  = (const float*)d_in[1];
    const float* qkv_b  = (const float*)d_in[2];
    const float* proj_w = (const float*)d_in[3];
    const float* proj_b = (const float*)d_in[4];
    const float* rel_h  = (const float*)d_in[5];
    const float* rel_w  = (const float*)d_in[6];
    float* out = (float*)d_out;

    float* qkv_ptr = nullptr;
    float* att_ptr = nullptr;
    cudaGetSymbolAddress((void**)&qkv_ptr, g_qkv);
    cudaGetSymbolAddress((void**)&att_ptr, g_att);

    // 1) QKV pointwise GEMM (tensor cores, 3xTF32): (2,96,HW) -> (2,288,HW)
    mma_gemm<288><<<dim3(HW / 256, 288 / 32, 2), 256>>>(x, qkv_w, qkv_b, qkv_ptr);

    // 2) Windowed halo attention with rel-pos + softmax -> (2,96,HW)
    attn_kernel<<<2 * NWIN * NWIN * 3, 128>>>(rel_h, rel_w);

    // 3) Output projection (tensor cores): (2,96,HW) -> (2,96,HW)
    mma_gemm<96><<<dim3(HW / 256, 96 / 32, 2), 256>>>(att_ptr, proj_w, proj_b, out);
}